// round 8
// baseline (speedup 1.0000x reference)
#include <cuda_runtime.h>

#define NDAYS  4
#define NHOURS 24
#define NDH    96          // NDAYS*NHOURS
#define NDH4   24          // NDH/4
#define NLINKS 2000
#define NPATHS 20000
#define NODS   4000
#define MAXL   64          // max links per path (mean ~10)
#define MAXP   320         // max paths per link (mean ~100)

// ---------------- device scratch ----------------
// Invariant: g_plc, g_lpc, g_denom are ZERO at entry to every kernel_launch.
// CUDA zero-initializes __device__ globals at module load; each pipeline run
// re-zeros them after last use (g_plc in k_vf, g_lpc/g_denom in k_out).
__device__ float          g_V[NLINKS][NDH];       // V transposed: [link][dh]
__device__ float          g_ev[NPATHS][NDH];      // exp(vf)
__device__ float          g_f[NPATHS][NDH];       // f = pf * q
__device__ float          g_denom[NODS * NDH];    // sum of exp(vf) per (od, dh)
__device__ int            g_plc[NPATHS];          // links-per-path counts
__device__ unsigned short g_pl[NPATHS][MAXL];     // CSC: link ids per path
__device__ int            g_lpc[NLINKS];          // paths-per-link counts
__device__ unsigned short g_lp[NLINKS][MAXP];     // CSR: path ids per link

// ---------------- kernel 1: V prologue + scan D (160 MB) + build CSC/CSR ----------------
__device__ __forceinline__ void sp_append(int l, int p) {
    int c1 = atomicAdd(&g_plc[p], 1);
    if (c1 < MAXL) g_pl[p][c1] = (unsigned short)l;
    int c2 = atomicAdd(&g_lpc[l], 1);
    if (c2 < MAXP) g_lp[l][c2] = (unsigned short)p;
}

__device__ __forceinline__ void sp_proc(unsigned x, unsigned y, unsigned z, unsigned w,
                                        int i, int pq) {
    if ((x | y | z | w) == 0u) return;
    int l = i / pq;
    int p = (i - l * pq) * 4;
    if (x) sp_append(l, p + 0);
    if (y) sp_append(l, p + 1);
    if (z) sp_append(l, p + 2);
    if (w) sp_append(l, p + 3);
}

__global__ void k_sparse(const uint4* __restrict__ D4,
                         const float* __restrict__ X,
                         const float* __restrict__ theta_raw,
                         const float* __restrict__ theta_links) {
    int tid = blockIdx.x * blockDim.x + threadIdx.x;

    // ---- prologue: compute V (0.77 MB of work, hides under the DRAM scan) ----
    if (tid < NDH * NLINKS) {
        int dh = tid / NLINKS;
        int l  = tid - dh * NLINKS;
        float t0 = fminf(theta_raw[0], 0.0f);
        float t1 = fminf(theta_raw[1], 0.0f);
        float t2 = fminf(theta_raw[2], 0.0f);
        float t3 = fminf(theta_raw[3], 0.0f);
        const float* xp = X + ((size_t)dh * NLINKS + l) * 5;
        g_V[l][dh] = xp[1] * t0 + xp[2] * t1 + xp[3] * t2 + xp[4] * t3 + theta_links[l];
    }

    // ---- main: streaming scan of D, append nonzeros (counters pre-zeroed) ----
    const int pq = NPATHS / 4;
    const int nt = (NLINKS * (NPATHS / 4)) / 4;   // 2.5M thread-slots of 4x uint4
    int S = gridDim.x * blockDim.x;
    for (int t = tid; t < nt; t += S) {
        int j = 4 * t;
        uint4 v0 = __ldcs(&D4[j + 0]);
        uint4 v1 = __ldcs(&D4[j + 1]);
        uint4 v2 = __ldcs(&D4[j + 2]);
        uint4 v3 = __ldcs(&D4[j + 3]);
        unsigned any = v0.x | v0.y | v0.z | v0.w | v1.x | v1.y | v1.z | v1.w |
                       v2.x | v2.y | v2.z | v2.w | v3.x | v3.y | v3.z | v3.w;
        if (any == 0u) continue;
        sp_proc(v0.x, v0.y, v0.z, v0.w, j + 0, pq);
        sp_proc(v1.x, v1.y, v1.z, v1.w, j + 1, pq);
        sp_proc(v2.x, v2.y, v2.z, v2.w, j + 2, pq);
        sp_proc(v3.x, v3.y, v3.z, v3.w, j + 3, pq);
    }
}

// ---------------- kernel 2: vf gather -> ev + denom accumulation ----------------
// No max-subtraction needed: vf in ~[-60, +2], exp(vf) never under/overflows fp32.
__global__ void k_vf(const int* __restrict__ od_of_path) {
    int p  = blockIdx.x * 4 + threadIdx.y;   // block(96,4), grid 5000
    int dh = threadIdx.x;
    int cnt = min(g_plc[p], MAXL);
    __syncthreads();                          // all reads of g_plc done
    if (dh == 0) g_plc[p] = 0;                // restore zero-invariant for next run

    const ushort4* pl4 = (const ushort4*)g_pl[p];
    float a0 = 0.f, a1 = 0.f, a2 = 0.f, a3 = 0.f;
    int i = 0;
    for (; i + 4 <= cnt; i += 4) {
        ushort4 l4 = pl4[i >> 2];
        a0 += g_V[l4.x][dh];
        a1 += g_V[l4.y][dh];
        a2 += g_V[l4.z][dh];
        a3 += g_V[l4.w][dh];
    }
    for (; i < cnt; ++i) a0 += g_V[g_pl[p][i]][dh];
    float ev = __expf((a0 + a1) + (a2 + a3));
    g_ev[p][dh] = ev;
    int od = od_of_path[p];
    atomicAdd(&g_denom[od * NDH + dh], ev);   // fire-and-forget RED
}

// ---------------- kernel 3: vectorized f = ev * q^2 / denom ----------------
__global__ void k_scale(const float* __restrict__ q_sqrt,
                        const int*   __restrict__ od_of_path) {
    int idx = blockIdx.x * blockDim.x + threadIdx.x;   // NPATHS*NDH4 threads
    if (idx >= NPATHS * NDH4) return;
    int p  = idx / NDH4;
    int c  = (idx - p * NDH4) * 4;
    int od = od_of_path[p];
    float qv = q_sqrt[od];
    qv *= qv;
    float4 d = *(const float4*)&g_denom[od * NDH + c];
    float4 v = *(const float4*)&g_ev[p][c];
    float4 f;
    f.x = __fdividef(v.x * qv, d.x);
    f.y = __fdividef(v.y * qv, d.y);
    f.z = __fdividef(v.z * qv, d.z);
    f.w = __fdividef(v.w * qv, d.w);
    *(float4*)&g_f[p][c] = f;
}

// ---------------- kernel 4: x = relu(D f), BPR epilogue, write out ----------------
__global__ void k_out(const float* __restrict__ X,
                      const float* __restrict__ log_alpha,
                      const float* __restrict__ beta_raw,
                      const float* __restrict__ kcap,
                      float* __restrict__ out) {
    int l  = blockIdx.x * 2 + threadIdx.y;   // block(96,2), grid 1000
    int dh = threadIdx.x;
    int cnt = min(g_lpc[l], MAXP);
    __syncthreads();                          // all reads of g_lpc done
    if (dh == 0) g_lpc[l] = 0;                // restore zero-invariant

    // restore zero-invariant for g_denom (384k floats, 192k threads: 2 each)
    {
        int gtid = (blockIdx.x * 2 + threadIdx.y) * NDH + dh;   // 0..191999
        g_denom[gtid] = 0.0f;
        g_denom[gtid + NLINKS * NDH] = 0.0f;                     // +192000
    }

    const ushort4* lp4 = (const ushort4*)g_lp[l];
    float a0 = 0.f, a1 = 0.f, a2 = 0.f, a3 = 0.f;
    int i = 0;
    for (; i + 4 <= cnt; i += 4) {
        ushort4 p4 = lp4[i >> 2];
        a0 += g_f[p4.x][dh];
        a1 += g_f[p4.y][dh];
        a2 += g_f[p4.z][dh];
        a3 += g_f[p4.w][dh];
    }
    for (; i < cnt; ++i) a0 += g_f[g_lp[l][i]][dh];
    float x = fmaxf((a0 + a1) + (a2 + a3), 0.0f);

    float alpha = __expf(log_alpha[l]);
    float beta  = fminf(fmaxf(beta_raw[l], 1e-12f), 4.0f);
    float tt    = X[((size_t)dh * NLINKS + l) * 5];   // X[...,0]
    float ratio = x / kcap[l];
    out[(size_t)dh * NLINKS + l] = tt * (1.0f + alpha * __powf(ratio, beta));
}

// ---------------- launcher ----------------
extern "C" void kernel_launch(void* const* d_in, const int* in_sizes, int n_in,
                              void* d_out, int out_size) {
    const float* X           = (const float*)d_in[0];
    const float* theta_raw   = (const float*)d_in[1];
    const float* theta_links = (const float*)d_in[2];
    const float* q_sqrt      = (const float*)d_in[3];
    const float* log_alpha   = (const float*)d_in[4];
    const float* beta_raw    = (const float*)d_in[5];
    const float* kcap        = (const float*)d_in[6];
    const float* D           = (const float*)d_in[7];
    const int*   od_of_path  = (const int*)d_in[8];
    float*       out         = (float*)d_out;

    k_sparse<<<1216, 256>>>((const uint4*)D, X, theta_raw, theta_links);
    k_vf<<<NPATHS / 4, dim3(NDH, 4)>>>(od_of_path);
    k_scale<<<(NPATHS * NDH4 + 255) / 256, 256>>>(q_sqrt, od_of_path);
    k_out<<<NLINKS / 2, dim3(NDH, 2)>>>(X, log_alpha, beta_raw, kcap, out);
}

// round 9
// speedup vs baseline: 1.0692x; 1.0692x over previous
#include <cuda_runtime.h>

#define NDAYS  4
#define NHOURS 24
#define NDH    96          // NDAYS*NHOURS
#define NDH4   24          // NDH/4
#define NLINKS 2000
#define NPATHS 20000
#define NODS   4000
#define MAXL   64          // max links per path (mean ~10)
#define MAXP   320         // max paths per link (mean ~100)

// ---------------- device scratch ----------------
// Invariant: g_plc, g_lpc, g_denom are ZERO at entry to every kernel_launch.
// CUDA zero-initializes __device__ globals at module load; each run restores
// zeros after last use, with NO added barriers:
//   g_plc  -> zeroed in k_scale (k_scale never reads it)
//   g_lpc  -> copied to g_lpc2 + zeroed in k_scale; k_out reads the copy
//   g_denom-> zeroed in k_out   (k_out never reads it)
__device__ float          g_V[NLINKS][NDH];       // V transposed: [link][dh]
__device__ float          g_ev[NPATHS][NDH];      // exp(vf)
__device__ float          g_f[NPATHS][NDH];       // f = pf * q
__device__ float          g_denom[NODS * NDH];    // sum of exp(vf) per (od, dh)
__device__ int            g_plc[NPATHS];          // links-per-path counts
__device__ unsigned short g_pl[NPATHS][MAXL];     // CSC: link ids per path
__device__ int            g_lpc[NLINKS];          // paths-per-link counts
__device__ int            g_lpc2[NLINKS];         // snapshot for k_out
__device__ unsigned short g_lp[NLINKS][MAXP];     // CSR: path ids per link

// ---------------- kernel 1: V prologue + scan D (160 MB) + build CSC/CSR ----------------
__device__ __forceinline__ void sp_append(int l, int p) {
    int c1 = atomicAdd(&g_plc[p], 1);
    if (c1 < MAXL) g_pl[p][c1] = (unsigned short)l;
    int c2 = atomicAdd(&g_lpc[l], 1);
    if (c2 < MAXP) g_lp[l][c2] = (unsigned short)p;
}

__device__ __forceinline__ void sp_proc(unsigned x, unsigned y, unsigned z, unsigned w,
                                        int i, int pq) {
    if ((x | y | z | w) == 0u) return;
    int l = i / pq;
    int p = (i - l * pq) * 4;
    if (x) sp_append(l, p + 0);
    if (y) sp_append(l, p + 1);
    if (z) sp_append(l, p + 2);
    if (w) sp_append(l, p + 3);
}

__global__ void k_sparse(const uint4* __restrict__ D4,
                         const float* __restrict__ X,
                         const float* __restrict__ theta_raw,
                         const float* __restrict__ theta_links) {
    int tid = blockIdx.x * blockDim.x + threadIdx.x;

    // ---- prologue: compute V (0.77 MB of work, hides under the DRAM scan) ----
    if (tid < NDH * NLINKS) {
        int dh = tid / NLINKS;
        int l  = tid - dh * NLINKS;
        float t0 = fminf(theta_raw[0], 0.0f);
        float t1 = fminf(theta_raw[1], 0.0f);
        float t2 = fminf(theta_raw[2], 0.0f);
        float t3 = fminf(theta_raw[3], 0.0f);
        const float* xp = X + ((size_t)dh * NLINKS + l) * 5;
        g_V[l][dh] = xp[1] * t0 + xp[2] * t1 + xp[3] * t2 + xp[4] * t3 + theta_links[l];
    }

    // ---- main: streaming scan of D, append nonzeros (counters pre-zeroed) ----
    const int pq = NPATHS / 4;
    const int nt = (NLINKS * (NPATHS / 4)) / 4;   // 2.5M thread-slots of 4x uint4
    int S = gridDim.x * blockDim.x;
    for (int t = tid; t < nt; t += S) {
        int j = 4 * t;
        uint4 v0 = __ldcs(&D4[j + 0]);
        uint4 v1 = __ldcs(&D4[j + 1]);
        uint4 v2 = __ldcs(&D4[j + 2]);
        uint4 v3 = __ldcs(&D4[j + 3]);
        unsigned any = v0.x | v0.y | v0.z | v0.w | v1.x | v1.y | v1.z | v1.w |
                       v2.x | v2.y | v2.z | v2.w | v3.x | v3.y | v3.z | v3.w;
        if (any == 0u) continue;
        sp_proc(v0.x, v0.y, v0.z, v0.w, j + 0, pq);
        sp_proc(v1.x, v1.y, v1.z, v1.w, j + 1, pq);
        sp_proc(v2.x, v2.y, v2.z, v2.w, j + 2, pq);
        sp_proc(v3.x, v3.y, v3.z, v3.w, j + 3, pq);
    }
}

// ---------------- kernel 2: vf gather -> ev + denom accumulation ----------------
// No max-subtraction needed: vf in ~[-60, +2], exp(vf) never under/overflows fp32.
__global__ void k_vf(const int* __restrict__ od_of_path) {
    int p  = blockIdx.x * 4 + threadIdx.y;   // block(96,4), grid 5000
    int dh = threadIdx.x;
    int cnt = min(g_plc[p], MAXL);
    const ushort4* pl4 = (const ushort4*)g_pl[p];
    float a0 = 0.f, a1 = 0.f, a2 = 0.f, a3 = 0.f;
    int i = 0;
    for (; i + 4 <= cnt; i += 4) {
        ushort4 l4 = pl4[i >> 2];
        a0 += g_V[l4.x][dh];
        a1 += g_V[l4.y][dh];
        a2 += g_V[l4.z][dh];
        a3 += g_V[l4.w][dh];
    }
    for (; i < cnt; ++i) a0 += g_V[g_pl[p][i]][dh];
    float ev = __expf((a0 + a1) + (a2 + a3));
    g_ev[p][dh] = ev;
    int od = od_of_path[p];
    atomicAdd(&g_denom[od * NDH + dh], ev);   // fire-and-forget RED
}

// ---------------- kernel 3: vectorized f = ev * q^2 / denom  (+ counter cleanup) ----------------
__global__ void k_scale(const float* __restrict__ q_sqrt,
                        const int*   __restrict__ od_of_path) {
    int idx = blockIdx.x * blockDim.x + threadIdx.x;   // NPATHS*NDH4 threads

    // cleanup (no reader of these in this kernel; pure stores)
    if (idx < NPATHS) g_plc[idx] = 0;                    // dead after k_vf
    if (idx < NLINKS) { g_lpc2[idx] = g_lpc[idx]; g_lpc[idx] = 0; }  // snapshot for k_out

    if (idx >= NPATHS * NDH4) return;
    int p  = idx / NDH4;
    int c  = (idx - p * NDH4) * 4;
    int od = od_of_path[p];
    float qv = q_sqrt[od];
    qv *= qv;
    float4 d = *(const float4*)&g_denom[od * NDH + c];
    float4 v = *(const float4*)&g_ev[p][c];
    float4 f;
    f.x = __fdividef(v.x * qv, d.x);
    f.y = __fdividef(v.y * qv, d.y);
    f.z = __fdividef(v.z * qv, d.z);
    f.w = __fdividef(v.w * qv, d.w);
    *(float4*)&g_f[p][c] = f;
}

// ---------------- kernel 4: x = relu(D f), BPR epilogue, write out ----------------
__global__ void k_out(const float* __restrict__ X,
                      const float* __restrict__ log_alpha,
                      const float* __restrict__ beta_raw,
                      const float* __restrict__ kcap,
                      float* __restrict__ out) {
    int l  = blockIdx.x * 2 + threadIdx.y;   // block(96,2), grid 1000
    int dh = threadIdx.x;

    // cleanup: g_denom dead after k_scale; fire-and-forget, no barrier needed
    {
        int gtid = l * NDH + dh;                 // 0..191999
        g_denom[gtid] = 0.0f;
        g_denom[gtid + NLINKS * NDH] = 0.0f;     // covers 192000..383999
    }

    int cnt = min(g_lpc2[l], MAXP);
    const ushort4* lp4 = (const ushort4*)g_lp[l];
    float a0 = 0.f, a1 = 0.f, a2 = 0.f, a3 = 0.f;
    int i = 0;
    for (; i + 4 <= cnt; i += 4) {
        ushort4 p4 = lp4[i >> 2];
        a0 += g_f[p4.x][dh];
        a1 += g_f[p4.y][dh];
        a2 += g_f[p4.z][dh];
        a3 += g_f[p4.w][dh];
    }
    for (; i < cnt; ++i) a0 += g_f[g_lp[l][i]][dh];
    float x = fmaxf((a0 + a1) + (a2 + a3), 0.0f);

    float alpha = __expf(log_alpha[l]);
    float beta  = fminf(fmaxf(beta_raw[l], 1e-12f), 4.0f);
    float tt    = X[((size_t)dh * NLINKS + l) * 5];   // X[...,0]
    float ratio = x / kcap[l];
    out[(size_t)dh * NLINKS + l] = tt * (1.0f + alpha * __powf(ratio, beta));
}

// ---------------- launcher ----------------
extern "C" void kernel_launch(void* const* d_in, const int* in_sizes, int n_in,
                              void* d_out, int out_size) {
    const float* X           = (const float*)d_in[0];
    const float* theta_raw   = (const float*)d_in[1];
    const float* theta_links = (const float*)d_in[2];
    const float* q_sqrt      = (const float*)d_in[3];
    const float* log_alpha   = (const float*)d_in[4];
    const float* beta_raw    = (const float*)d_in[5];
    const float* kcap        = (const float*)d_in[6];
    const float* D           = (const float*)d_in[7];
    const int*   od_of_path  = (const int*)d_in[8];
    float*       out         = (float*)d_out;

    k_sparse<<<1216, 256>>>((const uint4*)D, X, theta_raw, theta_links);
    k_vf<<<NPATHS / 4, dim3(NDH, 4)>>>(od_of_path);
    k_scale<<<(NPATHS * NDH4 + 255) / 256, 256>>>(q_sqrt, od_of_path);
    k_out<<<NLINKS / 2, dim3(NDH, 2)>>>(X, log_alpha, beta_raw, kcap, out);
}